// round 6
// baseline (speedup 1.0000x reference)
#include <cuda_runtime.h>

#define B_ 4
#define L_ 2048
#define D_ 512
#define H_ 8
#define DH_ 64
#define M_ (B_ * L_)  // 8192

// Scratch (allocation-free rule: __device__ globals)
__device__ float g_qp[M_ * D_];
__device__ float g_kp[M_ * D_];
__device__ float g_vp[M_ * D_];
__device__ float g_oh[M_ * D_];
__device__ float g_rinv[B_ * H_ * L_];

// ---------------------------------------------------------------------------
// GEMM: Y[M,N] = X[M,K] @ W[N,K]^T + bias[N];  M=8192, N=K=512
// 64x64 block tile, 256 threads, 4x4 per thread, BK=16.
// ---------------------------------------------------------------------------
__global__ __launch_bounds__(256) void gemm_bias_kernel(
    const float* __restrict__ X, const float* __restrict__ W,
    const float* __restrict__ bias, float* __restrict__ Y) {
  const int K = 512, N = 512;
  __shared__ __align__(16) float Xs[64][20];   // [m][k], padded
  __shared__ __align__(16) float Ws[16][68];   // [k][n], padded (float4-aligned rows)

  int bm = blockIdx.x * 64, bn = blockIdx.y * 64;
  int tid = threadIdx.x;
  int ty = tid >> 4, tx = tid & 15;
  int lr = tid >> 2, lc = (tid & 3) * 4;   // loader: row 0..63, col offset {0,4,8,12}

  float acc[4][4] = {};

  for (int k0 = 0; k0 < K; k0 += 16) {
    float4 xv = *(const float4*)&X[(size_t)(bm + lr) * K + k0 + lc];
    Xs[lr][lc + 0] = xv.x; Xs[lr][lc + 1] = xv.y;
    Xs[lr][lc + 2] = xv.z; Xs[lr][lc + 3] = xv.w;
    float4 wv = *(const float4*)&W[(size_t)(bn + lr) * K + k0 + lc];
    Ws[lc + 0][lr] = wv.x; Ws[lc + 1][lr] = wv.y;
    Ws[lc + 2][lr] = wv.z; Ws[lc + 3][lr] = wv.w;
    __syncthreads();

#pragma unroll
    for (int kk = 0; kk < 16; kk++) {
      float a[4];
#pragma unroll
      for (int i = 0; i < 4; i++) a[i] = Xs[ty * 4 + i][kk];
      float4 bv = *(const float4*)&Ws[kk][tx * 4];
#pragma unroll
      for (int i = 0; i < 4; i++) {
        acc[i][0] += a[i] * bv.x;
        acc[i][1] += a[i] * bv.y;
        acc[i][2] += a[i] * bv.z;
        acc[i][3] += a[i] * bv.w;
      }
    }
    __syncthreads();
  }

  float4 bb = *(const float4*)&bias[bn + tx * 4];
#pragma unroll
  for (int i = 0; i < 4; i++) {
    float4 o;
    o.x = acc[i][0] + bb.x;
    o.y = acc[i][1] + bb.y;
    o.z = acc[i][2] + bb.z;
    o.w = acc[i][3] + bb.w;
    *(float4*)&Y[(size_t)(bm + ty * 4 + i) * N + bn + tx * 4] = o;
  }
}

// ---------------------------------------------------------------------------
// Fused attention: per (b,h) and 64 q-rows.
// S = Q K^T / 8 + mask*(-1e9);  p = exp(S) (unnormalized, exp(-1e9)=0);
// write p to attn gmem; accumulate O = p @ V; at end scale O by 1/rowsum
// and record 1/rowsum for the later attn-normalize pass.
// Tiles are 64x64: each of the 256 threads loads 4 float4s (16 floats).
// ---------------------------------------------------------------------------
__global__ __launch_bounds__(256) void attn_kernel(
    const int* __restrict__ mask, float* __restrict__ attn_out, int has_attn) {
  extern __shared__ __align__(16) float sm[];
  float* Qs = sm;               // [64 q][65]  (pad 65: conflict-free broadcast rows)
  float* Kt = sm + 64 * 65;     // [64 d][68]  K transposed: float4 along k
  float* Vs = Kt + 64 * 68;     // [64 k][68]  natural: float4 along d
  float* Ps = Vs + 64 * 68;     // [64 q][68]

  __shared__ float red[64][17];
  __shared__ float maskS[64];
  __shared__ float rinvS[64];

  int bh = blockIdx.y;
  int b = bh >> 3, h = bh & 7;
  int q0 = blockIdx.x * 64;
  int tid = threadIdx.x, ty = tid >> 4, tx = tid & 15;
  int lr = tid >> 2, lc = (tid & 3) * 4;

  // Load full 64x64 Q tile (head slice): Qs[q][d]
#pragma unroll
  for (int j = 0; j < 4; j++) {
    int c = lc + 16 * j;
    float4 qv = *(const float4*)&g_qp[(size_t)(b * L_ + q0 + lr) * D_ + h * DH_ + c];
    Qs[lr * 65 + c + 0] = qv.x; Qs[lr * 65 + c + 1] = qv.y;
    Qs[lr * 65 + c + 2] = qv.z; Qs[lr * 65 + c + 3] = qv.w;
  }

  float acc[4][4] = {};
  float psum[4] = {};

  for (int k0 = 0; k0 < L_; k0 += 64) {
    __syncthreads();  // Qs ready (iter 0) / prev-iter Kt,Vs,Ps consumed

#pragma unroll
    for (int j = 0; j < 4; j++) {
      int c = lc + 16 * j;
      float4 kv = *(const float4*)&g_kp[(size_t)(b * L_ + k0 + lr) * D_ + h * DH_ + c];
      Kt[(c + 0) * 68 + lr] = kv.x; Kt[(c + 1) * 68 + lr] = kv.y;
      Kt[(c + 2) * 68 + lr] = kv.z; Kt[(c + 3) * 68 + lr] = kv.w;
      float4 vv = *(const float4*)&g_vp[(size_t)(b * L_ + k0 + lr) * D_ + h * DH_ + c];
      *(float4*)&Vs[lr * 68 + c] = vv;
    }
    if (tid < 64) maskS[tid] = -1e9f * (float)mask[b * L_ + k0 + tid];
    __syncthreads();

    // S = Q K^T  (4x4 per thread)
    float s[4][4] = {};
#pragma unroll
    for (int d = 0; d < 64; d++) {
      float a[4];
#pragma unroll
      for (int i = 0; i < 4; i++) a[i] = Qs[(ty * 4 + i) * 65 + d];
      float4 bv = *(const float4*)&Kt[d * 68 + tx * 4];
#pragma unroll
      for (int i = 0; i < 4; i++) {
        s[i][0] += a[i] * bv.x;
        s[i][1] += a[i] * bv.y;
        s[i][2] += a[i] * bv.z;
        s[i][3] += a[i] * bv.w;
      }
    }

    float m0 = maskS[tx * 4 + 0], m1 = maskS[tx * 4 + 1];
    float m2 = maskS[tx * 4 + 2], m3 = maskS[tx * 4 + 3];
#pragma unroll
    for (int i = 0; i < 4; i++) {
      float p0 = __expf(s[i][0] * 0.125f + m0);
      float p1 = __expf(s[i][1] * 0.125f + m1);
      float p2 = __expf(s[i][2] * 0.125f + m2);
      float p3 = __expf(s[i][3] * 0.125f + m3);
      psum[i] += p0 + p1 + p2 + p3;
      float4 pv = make_float4(p0, p1, p2, p3);
      *(float4*)&Ps[(ty * 4 + i) * 68 + tx * 4] = pv;
      if (has_attn) {
        *(float4*)&attn_out[(size_t)(bh * L_ + q0 + ty * 4 + i) * L_ + k0 + tx * 4] = pv;
      }
    }
    __syncthreads();  // Ps ready

    // O += P @ V
#pragma unroll
    for (int kk = 0; kk < 64; kk++) {
      float p[4];
#pragma unroll
      for (int i = 0; i < 4; i++) p[i] = Ps[(ty * 4 + i) * 68 + kk];
      float4 vvv = *(const float4*)&Vs[kk * 68 + tx * 4];
#pragma unroll
      for (int i = 0; i < 4; i++) {
        acc[i][0] += p[i] * vvv.x;
        acc[i][1] += p[i] * vvv.y;
        acc[i][2] += p[i] * vvv.z;
        acc[i][3] += p[i] * vvv.w;
      }
    }
  }

  // Row-sum reduction across the 16 tx lanes
#pragma unroll
  for (int i = 0; i < 4; i++) red[ty * 4 + i][tx] = psum[i];
  __syncthreads();
  if (tid < 64) {
    float ssum = 0.f;
#pragma unroll
    for (int j = 0; j < 16; j++) ssum += red[tid][j];
    float inv = 1.0f / ssum;
    rinvS[tid] = inv;
    g_rinv[bh * L_ + q0 + tid] = inv;
  }
  __syncthreads();

#pragma unroll
  for (int i = 0; i < 4; i++) {
    float inv = rinvS[ty * 4 + i];
    float4 o = make_float4(acc[i][0] * inv, acc[i][1] * inv,
                           acc[i][2] * inv, acc[i][3] * inv);
    *(float4*)&g_oh[(size_t)(b * L_ + q0 + ty * 4 + i) * D_ + h * DH_ + tx * 4] = o;
  }
}

// ---------------------------------------------------------------------------
// Normalize attn in place: attn[row, :] *= g_rinv[row]
// ---------------------------------------------------------------------------
__global__ __launch_bounds__(256) void norm_attn_kernel(float* __restrict__ attn) {
  size_t idx = ((size_t)blockIdx.x * 256 + threadIdx.x) * 4;
  size_t row = idx >> 11;  // / 2048
  float inv = g_rinv[row];
  float4 v = *(float4*)&attn[idx];
  v.x *= inv; v.y *= inv; v.z *= inv; v.w *= inv;
  *(float4*)&attn[idx] = v;
}

// ---------------------------------------------------------------------------
extern "C" void kernel_launch(void* const* d_in, const int* in_sizes, int n_in,
                              void* d_out, int out_size) {
  const float* q    = (const float*)d_in[0];
  const float* k    = (const float*)d_in[1];
  const float* v    = (const float*)d_in[2];
  const int*   mask = (const int*)d_in[3];
  const float* wq_w = (const float*)d_in[4];
  const float* wq_b = (const float*)d_in[5];
  const float* wk_w = (const float*)d_in[6];
  const float* wk_b = (const float*)d_in[7];
  const float* wv_w = (const float*)d_in[8];
  const float* wv_b = (const float*)d_in[9];
  const float* wo_w = (const float*)d_in[10];
  const float* wo_b = (const float*)d_in[11];
  float* out = (float*)d_out;

  const long long OUT_N  = (long long)M_ * D_;                 // 4,194,304
  const long long ATTN_N = (long long)B_ * H_ * L_ * L_;       // 134,217,728
  int has_attn = ((long long)out_size >= OUT_N + ATTN_N) ? 1 : 0;
  float* attn = out + OUT_N;

  void *p_qp, *p_kp, *p_vp, *p_oh;
  cudaGetSymbolAddress(&p_qp, g_qp);
  cudaGetSymbolAddress(&p_kp, g_kp);
  cudaGetSymbolAddress(&p_vp, g_vp);
  cudaGetSymbolAddress(&p_oh, g_oh);

  dim3 gg(M_ / 64, D_ / 64);
  gemm_bias_kernel<<<gg, 256>>>(q, wq_w, wq_b, (float*)p_qp);
  gemm_bias_kernel<<<gg, 256>>>(k, wk_w, wk_b, (float*)p_kp);
  gemm_bias_kernel<<<gg, 256>>>(v, wv_w, wv_b, (float*)p_vp);

  int smem = (64 * 65 + 3 * 64 * 68) * (int)sizeof(float);  // 68,864 B
  cudaFuncSetAttribute(attn_kernel, cudaFuncAttributeMaxDynamicSharedMemorySize, smem);
  dim3 ga(L_ / 64, B_ * H_);
  attn_kernel<<<ga, 256, smem>>>(mask, attn, has_attn);

  if (has_attn) {
    norm_attn_kernel<<<(unsigned)(ATTN_N / 4 / 256), 256>>>(attn);
  }

  gemm_bias_kernel<<<gg, 256>>>((const float*)p_oh, wo_w, wo_b, out);
}